// round 3
// baseline (speedup 1.0000x reference)
#include <cuda_runtime.h>
#include <cuda_bf16.h>

// GELU161: out = gelu_tanh(x) * (1 + exp(log_alpha) * tanh(exp(log_sigma) * surp))
// surp = N/(2(N-1)) EXACTLY (double-argsort rank statistic is a permutation of
// {0..N-1} -> data-independent). N = B*T = numel/4096.
//
// R3: ILP=4 (front-batched 128-bit loads, MLP_eff~4) + streaming cache hints
// (__ldcs/__stcs: 256MB single-touch stream through a 126MB L2).

#define SQRT_2_OVER_PI 0.7978845608028654f
#define GELU_C 0.044715f
#define VPT 4          // float4s per thread
#define TPB 256        // threads per block

__device__ __forceinline__ float tanh_approx(float x) {
    float y;
    asm("tanh.approx.f32 %0, %1;" : "=f"(y) : "f"(x));
    return y;
}

__device__ __forceinline__ float gelu_tanh(float x) {
    float x3 = x * x * x;
    float t = tanh_approx(SQRT_2_OVER_PI * fmaf(GELU_C, x3, x));
    return 0.5f * x * (1.0f + t);
}

__global__ __launch_bounds__(TPB) void gelu_gate_kernel(
    const float4* __restrict__ x,
    const float* __restrict__ log_alpha,
    const float* __restrict__ log_sigma,
    float4* __restrict__ out,
    int nvec,
    float surp)
{
    // Tile of VPT*TPB float4s per block; coalesced: thread t handles
    // base + t, base + TPB + t, ... (consecutive 128B lines per warp).
    int base = blockIdx.x * (TPB * VPT) + threadIdx.x;

    // Front-batched loads -> MLP_eff ~= VPT outstanding LDG.128 per thread.
    float4 v[VPT];
#pragma unroll
    for (int j = 0; j < VPT; j++) {
        int idx = base + j * TPB;
        if (idx < nvec) v[j] = __ldcs(&x[idx]);
    }

    float alpha = __expf(__ldg(log_alpha));
    float sigma = __expf(__ldg(log_sigma));
    float gate  = 1.0f + alpha * tanh_approx(sigma * surp);

#pragma unroll
    for (int j = 0; j < VPT; j++) {
        int idx = base + j * TPB;
        if (idx < nvec) {
            float4 r;
            r.x = gelu_tanh(v[j].x) * gate;
            r.y = gelu_tanh(v[j].y) * gate;
            r.z = gelu_tanh(v[j].z) * gate;
            r.w = gelu_tanh(v[j].w) * gate;
            __stcs(&out[idx], r);
        }
    }
}

extern "C" void kernel_launch(void* const* d_in, const int* in_sizes, int n_in,
                              void* d_out, int out_size)
{
    const float* x  = (const float*)d_in[0];
    const float* la = (const float*)d_in[1];
    const float* ls = (const float*)d_in[2];
    float* out = (float*)d_out;

    long long total = (long long)in_sizes[0];
    const long long D = 4096;
    long long N = total / D;
    float surp = (float)((double)N / (2.0 * (double)(N - 1)));

    int nvec = (int)(total / 4);                         // 8,388,608
    int blocks = (nvec + TPB * VPT - 1) / (TPB * VPT);   // 8192

    gelu_gate_kernel<<<blocks, TPB>>>(
        (const float4*)x, la, ls, (float4*)out, nvec, surp);
}

// round 4
// speedup vs baseline: 1.0463x; 1.0463x over previous
#include <cuda_runtime.h>
#include <cuda_bf16.h>

// GELU161: out = gelu_tanh(x) * (1 + exp(log_alpha) * tanh(exp(log_sigma) * surp))
// surp = N/(2(N-1)) EXACTLY (double-argsort rank statistic is a permutation of
// {0..N-1} -> data-independent). N = B*T = numel/4096.
//
// R4: 256-bit global load/store (Blackwell LDG.E.256 / STG.E.256) — halve
// LSU instructions and L1tex wavefronts per byte. Plain cache policy (R3
// showed .cs hints neutral-to-negative). Exact-division flat launch.

#define SQRT_2_OVER_PI 0.7978845608028654f
#define GELU_C 0.044715f
#define TPB 256

__device__ __forceinline__ float tanh_approx(float x) {
    float y;
    asm("tanh.approx.f32 %0, %1;" : "=f"(y) : "f"(x));
    return y;
}

__device__ __forceinline__ float gelu_tanh(float x) {
    float x3 = x * x * x;
    float t = tanh_approx(SQRT_2_OVER_PI * fmaf(GELU_C, x3, x));
    return 0.5f * x * (1.0f + t);
}

__device__ __forceinline__ void ldg_v8(const float* p, float r[8]) {
    asm volatile(
        "ld.global.v8.f32 {%0,%1,%2,%3,%4,%5,%6,%7}, [%8];"
        : "=f"(r[0]), "=f"(r[1]), "=f"(r[2]), "=f"(r[3]),
          "=f"(r[4]), "=f"(r[5]), "=f"(r[6]), "=f"(r[7])
        : "l"(p));
}

__device__ __forceinline__ void stg_v8(float* p, const float r[8]) {
    asm volatile(
        "st.global.v8.f32 [%0], {%1,%2,%3,%4,%5,%6,%7,%8};"
        :: "l"(p),
           "f"(r[0]), "f"(r[1]), "f"(r[2]), "f"(r[3]),
           "f"(r[4]), "f"(r[5]), "f"(r[6]), "f"(r[7])
        : "memory");
}

__global__ __launch_bounds__(TPB) void gelu_gate_kernel(
    const float* __restrict__ x,
    const float* __restrict__ log_alpha,
    const float* __restrict__ log_sigma,
    float* __restrict__ out,
    int nchunk,          // number of 8-float chunks
    float surp)
{
    int i = blockIdx.x * TPB + threadIdx.x;   // grid sized for exact coverage
    long long off = (long long)i * 8;

    float v[8];
    ldg_v8(x + off, v);

    float alpha = __expf(__ldg(log_alpha));
    float sigma = __expf(__ldg(log_sigma));
    float gate  = 1.0f + alpha * tanh_approx(sigma * surp);

    float r[8];
#pragma unroll
    for (int j = 0; j < 8; j++) r[j] = gelu_tanh(v[j]) * gate;

    stg_v8(out + off, r);
}

// Fallback scalar-tail kernel in case total isn't divisible (not hit for the
// bench shape 4*2048*4096, but keeps the contract safe).
__global__ void tail_kernel(const float* __restrict__ x,
                            const float* __restrict__ log_alpha,
                            const float* __restrict__ log_sigma,
                            float* __restrict__ out,
                            long long start, long long total, float surp)
{
    long long i = start + blockIdx.x * blockDim.x + threadIdx.x;
    if (i >= total) return;
    float alpha = __expf(__ldg(log_alpha));
    float sigma = __expf(__ldg(log_sigma));
    float gate  = 1.0f + alpha * tanh_approx(sigma * surp);
    out[i] = gelu_tanh(x[i]) * gate;
}

extern "C" void kernel_launch(void* const* d_in, const int* in_sizes, int n_in,
                              void* d_out, int out_size)
{
    const float* x  = (const float*)d_in[0];
    const float* la = (const float*)d_in[1];
    const float* ls = (const float*)d_in[2];
    float* out = (float*)d_out;

    long long total = (long long)in_sizes[0];
    const long long D = 4096;
    long long N = total / D;
    float surp = (float)((double)N / (2.0 * (double)(N - 1)));

    long long nchunk = total / 8;                 // 4,194,304 for bench shape
    long long covered = nchunk * 8;

    int blocks = (int)((nchunk + TPB - 1) / TPB); // 16384
    if (blocks > 0)
        gelu_gate_kernel<<<blocks, TPB>>>(x, la, ls, out, (int)nchunk, surp);

    if (covered < total) {
        long long rem = total - covered;
        int tb = (int)((rem + 255) / 256);
        tail_kernel<<<tb, 256>>>(x, la, ls, out, covered, total, surp);
    }
}